// round 1
// baseline (speedup 1.0000x reference)
#include <cuda_runtime.h>

#define HW 4096
#define CIN 256
#define CQKV 1024
#define B_ 8
#define NH 8
#define BG 64

// ---------------- scratch (static device globals; no runtime alloc) ----------
__device__ float d_qkv[B_ * CQKV * HW];   // rows: q 0-255, k 256-511, v 512-1023
__device__ float d_invq[B_ * HW];
__device__ float d_invk[B_ * HW];
__device__ float d_kvpart[BG * 8 * 32 * 64];
__device__ float d_m[BG * 32];
__device__ float d_gate[BG * HW];
__device__ float d_Wf2[B_ * 256 * 256];
__device__ float d_Wqkv[CQKV * CIN];
__device__ float d_ball[CQKV];
__device__ float d_s[256];
__device__ float d_t[256];

// ---------------- K0: pack weights/biases, fold BN ---------------------------
__global__ void k0_prep(const float* __restrict__ Wq, const float* __restrict__ bq,
                        const float* __restrict__ Wk, const float* __restrict__ bk,
                        const float* __restrict__ Wv, const float* __restrict__ bv,
                        const float* __restrict__ bf,
                        const float* __restrict__ gamma, const float* __restrict__ beta,
                        const float* __restrict__ mean,  const float* __restrict__ var) {
    int idx = blockIdx.x * blockDim.x + threadIdx.x;
    if (idx < CQKV * CIN) {
        int r = idx / CIN, c = idx % CIN;
        float w;
        if (r < 256)      w = Wq[r * CIN + c];
        else if (r < 512) w = Wk[(r - 256) * CIN + c];
        else              w = Wv[(r - 512) * CIN + c];
        d_Wqkv[idx] = w;
    }
    if (idx < CQKV) {
        d_ball[idx] = (idx < 256) ? bq[idx] : (idx < 512) ? bk[idx - 256] : bv[idx - 512];
    }
    if (idx < 256) {
        float s = gamma[idx] * rsqrtf(var[idx] + 1e-5f);
        d_s[idx] = s;
        d_t[idx] = (bf[idx] - mean[idx]) * s + beta[idx];
    }
}

// ---------------- K1: QKV GEMM  C[b](1024x4096) = Wqkv @ X_b + bias ----------
__global__ __launch_bounds__(256) void k1_qkv(const float* __restrict__ x) {
    const int b = blockIdx.z;
    const float* __restrict__ Bmat = x + (size_t)b * CIN * HW;
    float* __restrict__ Cmat = d_qkv + (size_t)b * CQKV * HW;

    __shared__ float As[16][132];
    __shared__ float Bs[16][132];

    const int tid = threadIdx.x;
    const int tx = tid & 15, ty = tid >> 4;
    const int mbase = blockIdx.y * 128;
    const int nbase = blockIdx.x * 128;

    float acc[8][8] = {};

    for (int kt = 0; kt < CIN; kt += 16) {
#pragma unroll
        for (int s = 0; s < 2; s++) {
            int slot = tid + s * 256;
            int r  = slot >> 2;
            int c4 = (slot & 3) * 4;
            float4 av = *(const float4*)&d_Wqkv[(mbase + r) * CIN + kt + c4];
            As[c4 + 0][r] = av.x; As[c4 + 1][r] = av.y;
            As[c4 + 2][r] = av.z; As[c4 + 3][r] = av.w;
        }
#pragma unroll
        for (int s = 0; s < 2; s++) {
            int slot = tid + s * 256;
            int r  = slot >> 5;
            int c4 = (slot & 31) * 4;
            *(float4*)&Bs[r][c4] = *(const float4*)&Bmat[(kt + r) * HW + nbase + c4];
        }
        __syncthreads();
#pragma unroll
        for (int kk = 0; kk < 16; kk++) {
            float ra[8], rb[8];
            *(float4*)&ra[0] = *(const float4*)&As[kk][ty * 8];
            *(float4*)&ra[4] = *(const float4*)&As[kk][ty * 8 + 4];
            *(float4*)&rb[0] = *(const float4*)&Bs[kk][tx * 8];
            *(float4*)&rb[4] = *(const float4*)&Bs[kk][tx * 8 + 4];
#pragma unroll
            for (int i = 0; i < 8; i++)
#pragma unroll
                for (int j = 0; j < 8; j++)
                    acc[i][j] += ra[i] * rb[j];
        }
        __syncthreads();
    }
#pragma unroll
    for (int i = 0; i < 8; i++) {
        int gm = mbase + ty * 8 + i;
        float bias = d_ball[gm];
#pragma unroll
        for (int j = 0; j < 8; j += 4) {
            float4 o;
            o.x = acc[i][j] + bias;     o.y = acc[i][j + 1] + bias;
            o.z = acc[i][j + 2] + bias; o.w = acc[i][j + 3] + bias;
            *(float4*)&Cmat[(size_t)gm * HW + nbase + tx * 8 + j] = o;
        }
    }
}

// ---------------- K2: per-pixel pixelnorm factors for q and k ---------------
__global__ void k2_norms() {
    int idx = blockIdx.x * blockDim.x + threadIdx.x;  // b*HW + p
    int b = idx >> 12, p = idx & 4095;
    const float* base = d_qkv + (size_t)b * CQKV * HW + p;
    float sq = 0.f, sk = 0.f;
#pragma unroll 8
    for (int c = 0; c < 256; c++) {
        float qv = base[(size_t)c * HW];
        float kv = base[(size_t)(256 + c) * HW];
        sq += qv * qv;
        sk += kv * kv;
    }
    d_invq[idx] = rsqrtf(sq * (1.f / 256.f) + 1e-8f);
    d_invk[idx] = rsqrtf(sk * (1.f / 256.f) + 1e-8f);
}

// ---------------- K3a: per-head partial kv = (k*invk) @ v^T ------------------
__global__ __launch_bounds__(256) void k3a_kv() {
    int head  = blockIdx.y;  // 0..63
    int split = blockIdx.x;  // 0..7
    int b = head >> 3, h = head & 7;
    const float* __restrict__ kbase = d_qkv + (size_t)b * CQKV * HW + (size_t)(256 + h * 32) * HW;
    const float* __restrict__ vbase = d_qkv + (size_t)b * CQKV * HW + (size_t)(512 + h * 64) * HW;
    const float* __restrict__ ivk = d_invk + b * HW;

    __shared__ float ks[32][65];
    __shared__ float vs[64][65];

    int tid = threadIdx.x;
    int c  = tid >> 3;
    int C0 = (tid & 7) * 8;
    float acc[8] = {};
    int p0 = split * 512;

    for (int ch = 0; ch < 512; ch += 64) {
        int pb = p0 + ch;
#pragma unroll
        for (int s = 0; s < 8; s++) {
            int slot = tid + s * 256;
            int rr = slot >> 6, pp = slot & 63;
            ks[rr][pp] = kbase[(size_t)rr * HW + pb + pp] * ivk[pb + pp];
        }
#pragma unroll
        for (int s = 0; s < 16; s++) {
            int slot = tid + s * 256;
            int rr = slot >> 6, pp = slot & 63;
            vs[rr][pp] = vbase[(size_t)rr * HW + pb + pp];
        }
        __syncthreads();
#pragma unroll 4
        for (int pp = 0; pp < 64; pp++) {
            float kc = ks[c][pp];
#pragma unroll
            for (int j = 0; j < 8; j++)
                acc[j] += kc * vs[C0 + j][pp];
        }
        __syncthreads();
    }
    float* out = d_kvpart + (size_t)(head * 8 + split) * 2048;
#pragma unroll
    for (int j = 0; j < 8; j++)
        out[c * 64 + C0 + j] = acc[j];
}

// ---------------- K3b: reduce kv, pixelnorm, compute m and Wf2 ---------------
__global__ __launch_bounds__(256) void k3b_kvnorm(const float* __restrict__ Wf) {
    int head = blockIdx.x;
    int b = head >> 3, h = head & 7;
    __shared__ float skv[2048];
    __shared__ float nrm[64];
    int tid = threadIdx.x;
#pragma unroll
    for (int s = 0; s < 8; s++) {
        int idx = tid + s * 256;
        float sum = 0.f;
#pragma unroll
        for (int sp = 0; sp < 8; sp++)
            sum += d_kvpart[(size_t)(head * 8 + sp) * 2048 + idx];
        skv[idx] = sum;
    }
    __syncthreads();
    if (tid < 64) {
        float s = 0.f;
#pragma unroll
        for (int c = 0; c < 32; c++) { float v = skv[c * 64 + tid]; s += v * v; }
        nrm[tid] = rsqrtf(s * (1.f / 32.f) + 1e-8f);
    }
    __syncthreads();
#pragma unroll
    for (int s = 0; s < 8; s++) {
        int idx = tid + s * 256;
        skv[idx] *= nrm[idx & 63];
    }
    __syncthreads();
    if (tid < 32) {
        float s = 0.f;
#pragma unroll
        for (int C = 32; C < 64; C++) s += skv[tid * 64 + C];
        d_m[head * 32 + tid] = s * (1.f / 32.f);
    }
    // Wf2[o][h*32+c] = sum_{c'} Wf[o][h*32+c'] * kvn[c][c']
    int o = tid;
    float wf[32];
#pragma unroll
    for (int c2 = 0; c2 < 32; c2++) wf[c2] = Wf[o * 256 + h * 32 + c2];
    float* out = d_Wf2 + (size_t)b * 65536 + o * 256 + h * 32;
    for (int c = 0; c < 32; c++) {
        float s = 0.f;
#pragma unroll
        for (int c2 = 0; c2 < 32; c2++) s += wf[c2] * skv[c * 64 + c2];
        out[c] = s;
    }
}

// ---------------- K4: gate = softmax_p( (invq * q·m) / 64 ) per head --------
__global__ __launch_bounds__(256) void k4_gate() {
    int head = blockIdx.x;
    int b = head >> 3, h = head & 7;
    const float* __restrict__ qbase = d_qkv + (size_t)b * CQKV * HW + (size_t)(h * 32) * HW;
    const float* __restrict__ ivq = d_invq + b * HW;
    __shared__ float sm[32];
    __shared__ float red[256];
    int tid = threadIdx.x;
    if (tid < 32) sm[tid] = d_m[head * 32 + tid];
    __syncthreads();

    float z[16];
    float lmax = -1e30f;
#pragma unroll
    for (int i = 0; i < 16; i++) {
        int p = tid + i * 256;
        float s = 0.f;
#pragma unroll
        for (int c = 0; c < 32; c++) s += qbase[(size_t)c * HW + p] * sm[c];
        z[i] = s * ivq[p] * (1.f / 64.f);
        lmax = fmaxf(lmax, z[i]);
    }
    red[tid] = lmax; __syncthreads();
    for (int st = 128; st > 0; st >>= 1) {
        if (tid < st) red[tid] = fmaxf(red[tid], red[tid + st]);
        __syncthreads();
    }
    float gmax = red[0]; __syncthreads();
    float lsum = 0.f;
#pragma unroll
    for (int i = 0; i < 16; i++) { z[i] = __expf(z[i] - gmax); lsum += z[i]; }
    red[tid] = lsum; __syncthreads();
    for (int st = 128; st > 0; st >>= 1) {
        if (tid < st) red[tid] += red[tid + st];
        __syncthreads();
    }
    float inv = 1.f / red[0];
#pragma unroll
    for (int i = 0; i < 16; i++)
        d_gate[(size_t)head * HW + tid + i * 256] = z[i] * inv;
}

// ---------------- K6: y = relu( (Wf2_b @ z_b) * s + t ),  z = gate*invq*q ----
__global__ __launch_bounds__(256) void k6_final(float* __restrict__ out) {
    const int b = blockIdx.z;
    const float* __restrict__ A   = d_Wf2 + (size_t)b * 65536;
    const float* __restrict__ qb  = d_qkv + (size_t)b * CQKV * HW;  // q rows 0..255
    const float* __restrict__ ivq = d_invq + b * HW;
    const float* __restrict__ gt  = d_gate + (size_t)b * 8 * HW;
    float* __restrict__ Cmat = out + (size_t)b * 256 * HW;

    __shared__ float As[16][132];
    __shared__ float Bs[16][132];

    const int tid = threadIdx.x;
    const int tx = tid & 15, ty = tid >> 4;
    const int mbase = blockIdx.y * 128;
    const int nbase = blockIdx.x * 128;

    float acc[8][8] = {};

    for (int kt = 0; kt < 256; kt += 16) {
#pragma unroll
        for (int s = 0; s < 2; s++) {
            int slot = tid + s * 256;
            int r  = slot >> 2;
            int c4 = (slot & 3) * 4;
            float4 av = *(const float4*)&A[(mbase + r) * 256 + kt + c4];
            As[c4 + 0][r] = av.x; As[c4 + 1][r] = av.y;
            As[c4 + 2][r] = av.z; As[c4 + 3][r] = av.w;
        }
#pragma unroll
        for (int s = 0; s < 2; s++) {
            int slot = tid + s * 256;
            int r  = slot >> 5;
            int c4 = (slot & 31) * 4;
            int k  = kt + r;
            int hh = k >> 5;
            int p  = nbase + c4;
            float4 qv = *(const float4*)&qb[(size_t)k * HW + p];
            float4 iv = *(const float4*)&ivq[p];
            float4 gv = *(const float4*)&gt[(size_t)hh * HW + p];
            float4 bvv;
            bvv.x = qv.x * iv.x * gv.x; bvv.y = qv.y * iv.y * gv.y;
            bvv.z = qv.z * iv.z * gv.z; bvv.w = qv.w * iv.w * gv.w;
            *(float4*)&Bs[r][c4] = bvv;
        }
        __syncthreads();
#pragma unroll
        for (int kk = 0; kk < 16; kk++) {
            float ra[8], rb[8];
            *(float4*)&ra[0] = *(const float4*)&As[kk][ty * 8];
            *(float4*)&ra[4] = *(const float4*)&As[kk][ty * 8 + 4];
            *(float4*)&rb[0] = *(const float4*)&Bs[kk][tx * 8];
            *(float4*)&rb[4] = *(const float4*)&Bs[kk][tx * 8 + 4];
#pragma unroll
            for (int i = 0; i < 8; i++)
#pragma unroll
                for (int j = 0; j < 8; j++)
                    acc[i][j] += ra[i] * rb[j];
        }
        __syncthreads();
    }
#pragma unroll
    for (int i = 0; i < 8; i++) {
        int gm = mbase + ty * 8 + i;
        float s = d_s[gm], t = d_t[gm];
#pragma unroll
        for (int j = 0; j < 8; j += 4) {
            float4 o;
            o.x = fmaxf(acc[i][j + 0] * s + t, 0.f);
            o.y = fmaxf(acc[i][j + 1] * s + t, 0.f);
            o.z = fmaxf(acc[i][j + 2] * s + t, 0.f);
            o.w = fmaxf(acc[i][j + 3] * s + t, 0.f);
            *(float4*)&Cmat[(size_t)gm * HW + nbase + tx * 8 + j] = o;
        }
    }
}

// ---------------- launch ------------------------------------------------------
extern "C" void kernel_launch(void* const* d_in, const int* in_sizes, int n_in,
                              void* d_out, int out_size) {
    const float* x     = (const float*)d_in[0];
    const float* Wq    = (const float*)d_in[1];
    const float* bq    = (const float*)d_in[2];
    const float* Wk    = (const float*)d_in[3];
    const float* bk    = (const float*)d_in[4];
    const float* Wv    = (const float*)d_in[5];
    const float* bv    = (const float*)d_in[6];
    const float* Wf    = (const float*)d_in[7];
    const float* bf    = (const float*)d_in[8];
    const float* gamma = (const float*)d_in[9];
    const float* beta  = (const float*)d_in[10];
    const float* mean  = (const float*)d_in[11];
    const float* var   = (const float*)d_in[12];
    float* out = (float*)d_out;

    k0_prep<<<(CQKV * CIN + 255) / 256, 256>>>(Wq, bq, Wk, bk, Wv, bv, bf, gamma, beta, mean, var);
    k1_qkv<<<dim3(HW / 128, CQKV / 128, B_), 256>>>(x);
    k2_norms<<<(B_ * HW) / 256, 256>>>();
    k3a_kv<<<dim3(8, BG), 256>>>();
    k3b_kvnorm<<<BG, 256>>>(Wf);
    k4_gate<<<BG, 256>>>();
    k6_final<<<dim3(HW / 128, 256 / 128, B_), 256>>>(out);
}

// round 3
// speedup vs baseline: 1.8838x; 1.8838x over previous
#include <cuda_runtime.h>
#include <cuda_bf16.h>
#include <cstdint>

#define HW 4096
#define B_ 8

// ---------------- scratch -----------------------------------------------------
__device__ float d_qkv[(size_t)B_ * 1024 * HW];
__device__ float d_invq[B_ * HW];
__device__ float d_invk[B_ * HW];
__device__ float d_kvpart[64 * 8 * 2048];
__device__ float d_m[64 * 32];
__device__ float d_gate[64 * HW];
__device__ float d_Wf2[B_ * 256 * 256];
__device__ float d_ball[1024];
__device__ float d_s[256];
__device__ float d_t[256];
__device__ __nv_bfloat16 d_Wq_h[1024 * 256], d_Wq_l[1024 * 256];
__device__ __nv_bfloat16 d_xT_h[(size_t)B_ * HW * 256], d_xT_l[(size_t)B_ * HW * 256];
__device__ __nv_bfloat16 d_zT_h[(size_t)B_ * HW * 256], d_zT_l[(size_t)B_ * HW * 256];
__device__ __nv_bfloat16 d_W2_h[B_ * 256 * 256], d_W2_l[B_ * 256 * 256];

// ---------------- helpers (sm_80-baseline PTX only) ----------------------------
__device__ __forceinline__ uint32_t smem_u32(const void* p) {
    uint32_t a;
    asm("{ .reg .u64 t; cvta.to.shared.u64 t, %1; cvt.u32.u64 %0, t; }" : "=r"(a) : "l"(p));
    return a;
}
__device__ __forceinline__ void cp16(uint32_t dst, const void* src) {
    asm volatile("cp.async.cg.shared.global [%0], [%1], 16;" :: "r"(dst), "l"(src));
}
#define CP_COMMIT() asm volatile("cp.async.commit_group;" ::: "memory")

__device__ __forceinline__ void ldsm4(uint32_t* r, uint32_t addr) {
    asm volatile("ldmatrix.sync.aligned.m8n8.x4.shared.b16 {%0,%1,%2,%3}, [%4];"
        : "=r"(r[0]), "=r"(r[1]), "=r"(r[2]), "=r"(r[3]) : "r"(addr));
}
__device__ __forceinline__ void mma16816(float* d, const uint32_t* a, uint32_t b0, uint32_t b1) {
    asm volatile("mma.sync.aligned.m16n8k16.row.col.f32.bf16.bf16.f32 "
        "{%0,%1,%2,%3}, {%4,%5,%6,%7}, {%8,%9}, {%0,%1,%2,%3};"
        : "+f"(d[0]), "+f"(d[1]), "+f"(d[2]), "+f"(d[3])
        : "r"(a[0]), "r"(a[1]), "r"(a[2]), "r"(a[3]), "r"(b0), "r"(b1));
}

// ---------------- K0: pack weights hi/lo, biases, BN fold ----------------------
__global__ void k0_prep(const float* __restrict__ Wq, const float* __restrict__ bq,
                        const float* __restrict__ Wk, const float* __restrict__ bk,
                        const float* __restrict__ Wv, const float* __restrict__ bv,
                        const float* __restrict__ bf,
                        const float* __restrict__ gamma, const float* __restrict__ beta,
                        const float* __restrict__ mean,  const float* __restrict__ var) {
    int idx = blockIdx.x * blockDim.x + threadIdx.x;
    if (idx < 1024 * 256) {
        int r = idx >> 8, c = idx & 255;
        float w = (r < 256) ? Wq[r * 256 + c] : (r < 512) ? Wk[(r - 256) * 256 + c] : Wv[(r - 512) * 256 + c];
        __nv_bfloat16 h = __float2bfloat16(w);
        d_Wq_h[idx] = h;
        d_Wq_l[idx] = __float2bfloat16(w - __bfloat162float(h));
    }
    if (idx < 1024)
        d_ball[idx] = (idx < 256) ? bq[idx] : (idx < 512) ? bk[idx - 256] : bv[idx - 512];
    if (idx < 256) {
        float s = gamma[idx] * rsqrtf(var[idx] + 1e-5f);
        d_s[idx] = s;
        d_t[idx] = (bf[idx] - mean[idx]) * s + beta[idx];
    }
}

// ---------------- convert x -> xT hi/lo (transpose + split) --------------------
__global__ __launch_bounds__(256) void k_convx(const float* __restrict__ x) {
    __shared__ float t[32][33];
    int p0 = blockIdx.x * 32, c0 = blockIdx.y * 32, b = blockIdx.z;
    int tx = threadIdx.x & 31, ty = threadIdx.x >> 5;
    const float* src = x + ((size_t)b * 256 + c0) * HW + p0;
#pragma unroll
    for (int i = 0; i < 4; i++) { int c = ty + i * 8; t[c][tx] = src[(size_t)c * HW + tx]; }
    __syncthreads();
    size_t ob = ((size_t)b * HW + p0) * 256 + c0;
#pragma unroll
    for (int i = 0; i < 4; i++) {
        int p = ty + i * 8;
        float v = t[tx][p];
        __nv_bfloat16 h = __float2bfloat16(v);
        d_xT_h[ob + (size_t)p * 256 + tx] = h;
        d_xT_l[ob + (size_t)p * 256 + tx] = __float2bfloat16(v - __bfloat162float(h));
    }
}

// ---------------- convert z = gate*invq*q -> zT hi/lo --------------------------
__global__ __launch_bounds__(256) void k_convz() {
    __shared__ float t[32][33];
    int p0 = blockIdx.x * 32, c0 = blockIdx.y * 32, b = blockIdx.z;
    int tx = threadIdx.x & 31, ty = threadIdx.x >> 5;
    const float* src = d_qkv + ((size_t)b * 1024 + c0) * HW + p0;
#pragma unroll
    for (int i = 0; i < 4; i++) { int c = ty + i * 8; t[c][tx] = src[(size_t)c * HW + tx]; }
    __syncthreads();
    const float* ivq = d_invq + b * HW;
    const float* g = d_gate + ((size_t)(b * 8) + (c0 >> 5)) * HW;
    size_t ob = ((size_t)b * HW + p0) * 256 + c0;
#pragma unroll
    for (int i = 0; i < 4; i++) {
        int p = ty + i * 8, pp = p0 + p;
        float v = t[tx][p] * (ivq[pp] * g[pp]);
        __nv_bfloat16 h = __float2bfloat16(v);
        d_zT_h[ob + (size_t)p * 256 + tx] = h;
        d_zT_l[ob + (size_t)p * 256 + tx] = __float2bfloat16(v - __bfloat162float(h));
    }
}

// ---------------- convert Wf2 -> hi/lo ------------------------------------------
__global__ void k_convw2() {
    int idx = blockIdx.x * blockDim.x + threadIdx.x;
    float v = d_Wf2[idx];
    __nv_bfloat16 h = __float2bfloat16(v);
    d_W2_h[idx] = h;
    d_W2_l[idx] = __float2bfloat16(v - __bfloat162float(h));
}

// ---------------- mma.sync GEMM (MODE 0: qkv, MODE 1: final) --------------------
// C[M x 4096] = A[M x 256] * B[4096 x 256]^T, bf16 hi/lo, terms AhBh+AhBl+AlBh.
// Block 128x128, 8 warps (2x4), warp tile 64x32, K-chunk 32, 2-stage cp.async.
// SMEM tile: 128 rows x 32 halves, pitch 80B (ldmatrix conflict-free).
#define PITCH 80
#define TILE_BYTES (128 * PITCH)
#define SM_TILE(s, t) (((s) * 4 + (t)) * TILE_BYTES)
#define SMEM_SZ (8 * TILE_BYTES)

template <int MODE>
__global__ __launch_bounds__(256, 1) void k_mma(float* __restrict__ CoutExt) {
    extern __shared__ char smem[];
    uint32_t sb = smem_u32(smem);
    const int tid = threadIdx.x;
    const int lane = tid & 31;
    const int wid = tid >> 5;
    const int wm = wid >> 2, wn = wid & 3;     // warp grid 2x4
    const int m0w = wm * 64, n0w = wn * 32;
    const int b = blockIdx.z;
    const int nbase = blockIdx.x * 128;
    const int mbase = blockIdx.y * 128;
    const int Mtot = (MODE == 0) ? 1024 : 256;

    const __nv_bfloat16* Ah = (MODE == 0) ? d_Wq_h : d_W2_h + (size_t)b * 65536;
    const __nv_bfloat16* Al = (MODE == 0) ? d_Wq_l : d_W2_l + (size_t)b * 65536;
    const __nv_bfloat16* Bh = ((MODE == 0) ? d_xT_h : d_zT_h) + (size_t)b * HW * 256;
    const __nv_bfloat16* Bl = ((MODE == 0) ? d_xT_l : d_zT_l) + (size_t)b * HW * 256;
    float* Cg = (MODE == 0) ? d_qkv + (size_t)b * 1024 * HW : CoutExt + (size_t)b * 256 * HW;

    const __nv_bfloat16* bases[4] = {Ah + (size_t)mbase * 256, Al + (size_t)mbase * 256,
                                     Bh + (size_t)nbase * 256, Bl + (size_t)nbase * 256};

    // loader: 4 tiles x 128 rows x 4 chunks(16B) = 2048 / 256 thr = 8 each
    auto load_chunk = [&](int kc, int s) {
#pragma unroll
        for (int j = 0; j < 8; j++) {
            int g = tid + j * 256;
            int t = g >> 9, w = g & 511;
            int r = w >> 2, c = w & 3;
            const char* src = (const char*)bases[t] + ((size_t)r * 256 + kc * 32 + c * 8) * 2;
            cp16(sb + SM_TILE(s, t) + r * PITCH + c * 16, src);
        }
        CP_COMMIT();
    };

    float acc[4][4][4] = {};

    // ldmatrix per-thread address components
    const int a_row = lane & 15;
    const int a_colh = (lane >> 4) << 3;                 // 0 or 8 halves
    const int b_row = (lane & 7) + ((lane >> 4) << 3);
    const int b_colh = ((lane >> 3) & 1) << 3;

    load_chunk(0, 0);
    load_chunk(1, 1);

#pragma unroll
    for (int i = 0; i < 8; i++) {
        const int s = i & 1;
        if (i < 6) asm volatile("cp.async.wait_group 1;" ::: "memory");
        else       asm volatile("cp.async.wait_group 0;" ::: "memory");
        __syncthreads();

        const uint32_t tAh = sb + SM_TILE(s, 0), tAl = sb + SM_TILE(s, 1);
        const uint32_t tBh = sb + SM_TILE(s, 2), tBl = sb + SM_TILE(s, 3);
#pragma unroll
        for (int ks = 0; ks < 2; ks++) {
            const int kh = ks * 16;
            uint32_t aH[4][4], aL[4][4], bH[4][2], bL[4][2];
#pragma unroll
            for (int mt = 0; mt < 4; mt++) {
                uint32_t off = (uint32_t)(m0w + mt * 16 + a_row) * PITCH + (kh + a_colh) * 2;
                ldsm4(aH[mt], tAh + off);
                ldsm4(aL[mt], tAl + off);
            }
#pragma unroll
            for (int bt = 0; bt < 2; bt++) {
                uint32_t off = (uint32_t)(n0w + bt * 16 + b_row) * PITCH + (kh + b_colh) * 2;
                uint32_t rh[4], rl[4];
                ldsm4(rh, tBh + off);
                ldsm4(rl, tBl + off);
                bH[bt * 2][0] = rh[0]; bH[bt * 2][1] = rh[1];
                bH[bt * 2 + 1][0] = rh[2]; bH[bt * 2 + 1][1] = rh[3];
                bL[bt * 2][0] = rl[0]; bL[bt * 2][1] = rl[1];
                bL[bt * 2 + 1][0] = rl[2]; bL[bt * 2 + 1][1] = rl[3];
            }
#pragma unroll
            for (int mt = 0; mt < 4; mt++)
#pragma unroll
                for (int nt = 0; nt < 4; nt++) {
                    mma16816(acc[mt][nt], aH[mt], bH[nt][0], bH[nt][1]);
                    mma16816(acc[mt][nt], aH[mt], bL[nt][0], bL[nt][1]);
                    mma16816(acc[mt][nt], aL[mt], bH[nt][0], bH[nt][1]);
                }
        }
        __syncthreads();
        if (i + 2 < 8) load_chunk(i + 2, s);
    }

    // epilogue
#pragma unroll
    for (int mt = 0; mt < 4; mt++) {
        int r0 = mbase + m0w + mt * 16 + (lane >> 2);
        int r1 = r0 + 8;
        float b0, sc0, t0, b1, sc1, t1;
        if (MODE == 0) { b0 = d_ball[r0]; b1 = d_ball[r1]; }
        else { sc0 = d_s[r0]; t0 = d_t[r0]; sc1 = d_s[r1]; t1 = d_t[r1]; }
#pragma unroll
        for (int nt = 0; nt < 4; nt++) {
            int c = nbase + n0w + nt * 8 + (lane & 3) * 2;
            float2 o0, o1;
            if (MODE == 0) {
                o0.x = acc[mt][nt][0] + b0; o0.y = acc[mt][nt][1] + b0;
                o1.x = acc[mt][nt][2] + b1; o1.y = acc[mt][nt][3] + b1;
            } else {
                o0.x = fmaxf(acc[mt][nt][0] * sc0 + t0, 0.f);
                o0.y = fmaxf(acc[mt][nt][1] * sc0 + t0, 0.f);
                o1.x = fmaxf(acc[mt][nt][2] * sc1 + t1, 0.f);
                o1.y = fmaxf(acc[mt][nt][3] * sc1 + t1, 0.f);
            }
            *(float2*)&Cg[(size_t)r0 * HW + c] = o0;
            *(float2*)&Cg[(size_t)r1 * HW + c] = o1;
        }
    }
}

// ---------------- K2: pixelnorm factors ---------------------------------------
__global__ void k2_norms() {
    int idx = blockIdx.x * blockDim.x + threadIdx.x;
    int b = idx >> 12;
    const float* base = d_qkv + (size_t)b * 1024 * HW + (idx & 4095);
    float sq = 0.f, sk = 0.f;
#pragma unroll 8
    for (int c = 0; c < 256; c++) {
        float qv = base[(size_t)c * HW];
        float kv = base[(size_t)(256 + c) * HW];
        sq += qv * qv;
        sk += kv * kv;
    }
    d_invq[idx] = rsqrtf(sq * (1.f / 256.f) + 1e-8f);
    d_invk[idx] = rsqrtf(sk * (1.f / 256.f) + 1e-8f);
}

// ---------------- K3a: per-head partial kv = (k*invk) @ v^T --------------------
__global__ __launch_bounds__(256) void k3a_kv() {
    int head = blockIdx.y, split = blockIdx.x;
    int b = head >> 3, h = head & 7;
    const float* __restrict__ kb = d_qkv + ((size_t)b * 1024 + 256 + h * 32) * HW;
    const float* __restrict__ vb = d_qkv + ((size_t)b * 1024 + 512 + h * 64) * HW;
    const float* __restrict__ ivk = d_invk + b * HW;

    __shared__ float ks[32][64];
    __shared__ float vsT[64][68];

    int tid = threadIdx.x;
    int tx = tid & 15, ty = tid >> 4;
    float acc[2][4] = {};
    int p0 = split * 512;

    for (int ch = 0; ch < 512; ch += 64) {
        int pb = p0 + ch;
#pragma unroll
        for (int s = 0; s < 8; s++) {
            int slot = tid + s * 256;
            int c = slot >> 6, p = slot & 63;
            ks[c][p] = kb[(size_t)c * HW + pb + p] * ivk[pb + p];
        }
#pragma unroll
        for (int s = 0; s < 16; s++) {
            int slot = tid + s * 256;
            int C = slot >> 6, p = slot & 63;
            vsT[p][C] = vb[(size_t)C * HW + pb + p];
        }
        __syncthreads();
#pragma unroll 4
        for (int p = 0; p < 64; p++) {
            float4 v4 = *(const float4*)&vsT[p][tx * 4];
            float k0 = ks[ty * 2][p], k1 = ks[ty * 2 + 1][p];
            acc[0][0] += k0 * v4.x; acc[0][1] += k0 * v4.y;
            acc[0][2] += k0 * v4.z; acc[0][3] += k0 * v4.w;
            acc[1][0] += k1 * v4.x; acc[1][1] += k1 * v4.y;
            acc[1][2] += k1 * v4.z; acc[1][3] += k1 * v4.w;
        }
        __syncthreads();
    }
    float* out = d_kvpart + ((size_t)head * 8 + split) * 2048;
#pragma unroll
    for (int i = 0; i < 2; i++)
#pragma unroll
        for (int j = 0; j < 4; j++)
            out[(ty * 2 + i) * 64 + tx * 4 + j] = acc[i][j];
}

// ---------------- K3b: reduce kv, pixelnorm, m, Wf2 ----------------------------
__global__ __launch_bounds__(256) void k3b_kvnorm(const float* __restrict__ Wf) {
    int head = blockIdx.x;
    int b = head >> 3, h = head & 7;
    __shared__ float skv[2048];
    __shared__ float nrm[64];
    int tid = threadIdx.x;
#pragma unroll
    for (int s = 0; s < 8; s++) {
        int idx = tid + s * 256;
        float sum = 0.f;
#pragma unroll
        for (int sp = 0; sp < 8; sp++)
            sum += d_kvpart[(size_t)(head * 8 + sp) * 2048 + idx];
        skv[idx] = sum;
    }
    __syncthreads();
    if (tid < 64) {
        float s = 0.f;
#pragma unroll
        for (int c = 0; c < 32; c++) { float v = skv[c * 64 + tid]; s += v * v; }
        nrm[tid] = rsqrtf(s * (1.f / 32.f) + 1e-8f);
    }
    __syncthreads();
#pragma unroll
    for (int s = 0; s < 8; s++) {
        int idx = tid + s * 256;
        skv[idx] *= nrm[idx & 63];
    }
    __syncthreads();
    if (tid < 32) {
        float s = 0.f;
#pragma unroll
        for (int C = 32; C < 64; C++) s += skv[tid * 64 + C];
        d_m[head * 32 + tid] = s * (1.f / 32.f);
    }
    int o = tid;
    float wf[32];
#pragma unroll
    for (int c2 = 0; c2 < 32; c2++) wf[c2] = Wf[o * 256 + h * 32 + c2];
    float* out = d_Wf2 + (size_t)b * 65536 + o * 256 + h * 32;
    for (int c = 0; c < 32; c++) {
        float s = 0.f;
#pragma unroll
        for (int c2 = 0; c2 < 32; c2++) s += wf[c2] * skv[c * 64 + c2];
        out[c] = s;
    }
}

// ---------------- K4: spatial softmax gate -------------------------------------
__global__ __launch_bounds__(256) void k4_gate() {
    int head = blockIdx.x;
    int b = head >> 3, h = head & 7;
    const float* __restrict__ qbase = d_qkv + ((size_t)b * 1024 + h * 32) * HW;
    const float* __restrict__ ivq = d_invq + b * HW;
    __shared__ float sm[32];
    __shared__ float red[256];
    int tid = threadIdx.x;
    if (tid < 32) sm[tid] = d_m[head * 32 + tid];
    __syncthreads();

    float z[16];
    float lmax = -1e30f;
#pragma unroll
    for (int i = 0; i < 16; i++) {
        int p = tid + i * 256;
        float s = 0.f;
#pragma unroll
        for (int c = 0; c < 32; c++) s += qbase[(size_t)c * HW + p] * sm[c];
        z[i] = s * ivq[p] * (1.f / 64.f);
        lmax = fmaxf(lmax, z[i]);
    }
    red[tid] = lmax; __syncthreads();
    for (int st = 128; st > 0; st >>= 1) {
        if (tid < st) red[tid] = fmaxf(red[tid], red[tid + st]);
        __syncthreads();
    }
    float gmax = red[0]; __syncthreads();
    float lsum = 0.f;
#pragma unroll
    for (int i = 0; i < 16; i++) { z[i] = __expf(z[i] - gmax); lsum += z[i]; }
    red[tid] = lsum; __syncthreads();
    for (int st = 128; st > 0; st >>= 1) {
        if (tid < st) red[tid] += red[tid + st];
        __syncthreads();
    }
    float inv = 1.f / red[0];
#pragma unroll
    for (int i = 0; i < 16; i++)
        d_gate[(size_t)head * HW + tid + i * 256] = z[i] * inv;
}

// ---------------- launch --------------------------------------------------------
extern "C" void kernel_launch(void* const* d_in, const int* in_sizes, int n_in,
                              void* d_out, int out_size) {
    const float* x     = (const float*)d_in[0];
    const float* Wq    = (const float*)d_in[1];
    const float* bq    = (const float*)d_in[2];
    const float* Wk    = (const float*)d_in[3];
    const float* bk    = (const float*)d_in[4];
    const float* Wv    = (const float*)d_in[5];
    const float* bv    = (const float*)d_in[6];
    const float* Wf    = (const float*)d_in[7];
    const float* bf    = (const float*)d_in[8];
    const float* gamma = (const float*)d_in[9];
    const float* beta  = (const float*)d_in[10];
    const float* mean  = (const float*)d_in[11];
    const float* var   = (const float*)d_in[12];
    float* out = (float*)d_out;

    static bool attr_set = false;
    if (!attr_set) {
        cudaFuncSetAttribute(k_mma<0>, cudaFuncAttributeMaxDynamicSharedMemorySize, SMEM_SZ);
        cudaFuncSetAttribute(k_mma<1>, cudaFuncAttributeMaxDynamicSharedMemorySize, SMEM_SZ);
        attr_set = true;
    }

    k0_prep<<<(1024 * 256 + 255) / 256, 256>>>(Wq, bq, Wk, bk, Wv, bv, bf, gamma, beta, mean, var);
    k_convx<<<dim3(128, 8, B_), 256>>>(x);
    k_mma<0><<<dim3(32, 8, B_), 256, SMEM_SZ>>>(nullptr);
    k2_norms<<<(B_ * HW) / 256, 256>>>();
    k3a_kv<<<dim3(8, 64), 256>>>();
    k3b_kvnorm<<<64, 256>>>(Wf);
    k_convw2<<<(B_ * 65536) / 256, 256>>>();
    k4_gate<<<64, 256>>>();
    k_convz<<<dim3(128, 8, B_), 256>>>();
    k_mma<1><<<dim3(32, 2, B_), 256, SMEM_SZ>>>(out);
}

// round 4
// speedup vs baseline: 2.2308x; 1.1842x over previous
#include <cuda_runtime.h>
#include <cuda_bf16.h>
#include <cstdint>

#define HW 4096
#define B_ 8

// ---------------- scratch -----------------------------------------------------
__device__ float d_qkvT[(size_t)B_ * HW * 1024];   // pixel-major: [b][p][ch] ch: q0-255,k256-511,v512-1023
__device__ float d_ssqp[4 * B_ * HW];              // partial ssq: tiles q0,q1,k0,k1
__device__ float d_invq[B_ * HW];
__device__ float d_invk[B_ * HW];
__device__ float d_kvpart[64 * 8 * 2048];
__device__ float d_m[64 * 32];
__device__ float d_gate[64 * HW];
__device__ float d_Wf2[B_ * 256 * 256];
__device__ float d_ball[1024];
__device__ float d_s[256];
__device__ float d_t[256];
__device__ __nv_bfloat16 d_Wq_h[1024 * 256], d_Wq_l[1024 * 256];
__device__ __nv_bfloat16 d_xT_h[(size_t)B_ * HW * 256], d_xT_l[(size_t)B_ * HW * 256];
__device__ __nv_bfloat16 d_W2_h[B_ * 256 * 256], d_W2_l[B_ * 256 * 256];

// ---------------- helpers (sm_80-baseline PTX only) ----------------------------
__device__ __forceinline__ uint32_t smem_u32(const void* p) {
    uint32_t a;
    asm("{ .reg .u64 t; cvta.to.shared.u64 t, %1; cvt.u32.u64 %0, t; }" : "=r"(a) : "l"(p));
    return a;
}
__device__ __forceinline__ void cp16(uint32_t dst, const void* src) {
    asm volatile("cp.async.cg.shared.global [%0], [%1], 16;" :: "r"(dst), "l"(src));
}
#define CP_COMMIT() asm volatile("cp.async.commit_group;" ::: "memory")

__device__ __forceinline__ void ldsm4(uint32_t* r, uint32_t addr) {
    asm volatile("ldmatrix.sync.aligned.m8n8.x4.shared.b16 {%0,%1,%2,%3}, [%4];"
        : "=r"(r[0]), "=r"(r[1]), "=r"(r[2]), "=r"(r[3]) : "r"(addr));
}
__device__ __forceinline__ void mma16816(float* d, const uint32_t* a, uint32_t b0, uint32_t b1) {
    asm volatile("mma.sync.aligned.m16n8k16.row.col.f32.bf16.bf16.f32 "
        "{%0,%1,%2,%3}, {%4,%5,%6,%7}, {%8,%9}, {%0,%1,%2,%3};"
        : "+f"(d[0]), "+f"(d[1]), "+f"(d[2]), "+f"(d[3])
        : "r"(a[0]), "r"(a[1]), "r"(a[2]), "r"(a[3]), "r"(b0), "r"(b1));
}

// ---------------- K0: pack weights hi/lo, biases, BN fold ----------------------
__global__ void k0_prep(const float* __restrict__ Wq, const float* __restrict__ bq,
                        const float* __restrict__ Wk, const float* __restrict__ bk,
                        const float* __restrict__ Wv, const float* __restrict__ bv,
                        const float* __restrict__ bf,
                        const float* __restrict__ gamma, const float* __restrict__ beta,
                        const float* __restrict__ mean,  const float* __restrict__ var) {
    int idx = blockIdx.x * blockDim.x + threadIdx.x;
    if (idx < 1024 * 256) {
        int r = idx >> 8, c = idx & 255;
        float w = (r < 256) ? Wq[r * 256 + c] : (r < 512) ? Wk[(r - 256) * 256 + c] : Wv[(r - 512) * 256 + c];
        __nv_bfloat16 h = __float2bfloat16(w);
        d_Wq_h[idx] = h;
        d_Wq_l[idx] = __float2bfloat16(w - __bfloat162float(h));
    }
    if (idx < 1024)
        d_ball[idx] = (idx < 256) ? bq[idx] : (idx < 512) ? bk[idx - 256] : bv[idx - 512];
    if (idx < 256) {
        float s = gamma[idx] * rsqrtf(var[idx] + 1e-5f);
        d_s[idx] = s;
        d_t[idx] = (bf[idx] - mean[idx]) * s + beta[idx];
    }
}

// ---------------- convert x -> xT hi/lo (transpose + split, bf16x2 stores) -----
__global__ __launch_bounds__(256) void k_convx(const float* __restrict__ x) {
    __shared__ float t[64][33];
    int p0 = blockIdx.x * 32, c0 = blockIdx.y * 64, b = blockIdx.z;
    const float* src = x + ((size_t)b * 256 + c0) * HW + p0;
    int tid = threadIdx.x;
#pragma unroll
    for (int j = 0; j < 8; j++) {
        int idx = tid + j * 256;
        int cc = idx >> 5, pp = idx & 31;
        t[cc][pp] = src[(size_t)cc * HW + pp];
    }
    __syncthreads();
    __nv_bfloat162* oh = (__nv_bfloat162*)d_xT_h;
    __nv_bfloat162* ol = (__nv_bfloat162*)d_xT_l;
#pragma unroll
    for (int j = 0; j < 4; j++) {
        int idx = tid + j * 256;
        int p = idx >> 5, pr = idx & 31;
        float v0 = t[pr * 2][p], v1 = t[pr * 2 + 1][p];
        __nv_bfloat16 h0 = __float2bfloat16(v0), h1 = __float2bfloat16(v1);
        __nv_bfloat162 hh; hh.x = h0; hh.y = h1;
        __nv_bfloat162 ll;
        ll.x = __float2bfloat16(v0 - __bfloat162float(h0));
        ll.y = __float2bfloat16(v1 - __bfloat162float(h1));
        size_t o = ((size_t)b * HW + p0 + p) * 128 + (c0 >> 1) + pr;
        oh[o] = hh;
        ol[o] = ll;
    }
}

// ---------------- convert Wf2 -> hi/lo ------------------------------------------
__global__ void k_convw2() {
    int idx = blockIdx.x * blockDim.x + threadIdx.x;
    float v = d_Wf2[idx];
    __nv_bfloat16 h = __float2bfloat16(v);
    d_W2_h[idx] = h;
    d_W2_l[idx] = __float2bfloat16(v - __bfloat162float(h));
}

// ---------------- mma.sync GEMM ------------------------------------------------
// MODE 0: qkv = Wqkv @ x^T  -> writes d_qkvT transposed + partial ssq
// MODE 1: out = Wf2 @ z^T   -> B operand (z = gate*invq*q) folded in loader
// Block 128x128, 8 warps (2x4), warp tile 64x32, K-chunk 32, 2-stage cp.async.
#define PITCH 80
#define TILE_BYTES (128 * PITCH)
#define SM_TILE(s, t) (((s) * 4 + (t)) * TILE_BYTES)
#define SMEM_SZ (8 * TILE_BYTES)

template <int MODE>
__global__ __launch_bounds__(256, 1) void k_mma(float* __restrict__ CoutExt) {
    extern __shared__ char smem[];
    uint32_t sb = smem_u32(smem);
    const int tid = threadIdx.x;
    const int lane = tid & 31;
    const int wid = tid >> 5;
    const int wm = wid >> 2, wn = wid & 3;
    const int m0w = wm * 64, n0w = wn * 32;
    const int b = blockIdx.z;
    const int nbase = blockIdx.x * 128;
    const int mbase = blockIdx.y * 128;

    const __nv_bfloat16* Ah = (MODE == 0) ? d_Wq_h + (size_t)mbase * 256
                                          : d_W2_h + (size_t)b * 65536 + (size_t)mbase * 256;
    const __nv_bfloat16* Al = (MODE == 0) ? d_Wq_l + (size_t)mbase * 256
                                          : d_W2_l + (size_t)b * 65536 + (size_t)mbase * 256;
    const __nv_bfloat16* Bh = d_xT_h + (size_t)b * HW * 256 + (size_t)nbase * 256;
    const __nv_bfloat16* Bl = d_xT_l + (size_t)b * HW * 256 + (size_t)nbase * 256;

    const __nv_bfloat16* bases4[4] = {Ah, Al, Bh, Bl};
    const __nv_bfloat16* bases2[2] = {Ah, Al};

    // MODE 0 loader: 4 tiles (A hi/lo + B hi/lo) via cp.async
    auto load4 = [&](int kc, int s) {
#pragma unroll
        for (int j = 0; j < 8; j++) {
            int g = tid + j * 256;
            int t = g >> 9, w = g & 511;
            int r = w >> 2, c = w & 3;
            const char* src = (const char*)bases4[t] + ((size_t)r * 256 + kc * 32 + c * 8) * 2;
            cp16(sb + SM_TILE(s, t) + r * PITCH + c * 16, src);
        }
        CP_COMMIT();
    };
    // MODE 1 loader: A tiles only via cp.async
    auto loadA = [&](int kc, int s) {
#pragma unroll
        for (int j = 0; j < 4; j++) {
            int g = tid + j * 256;
            int t = g >> 9, w = g & 511;
            int r = w >> 2, c = w & 3;
            const char* src = (const char*)bases2[t] + ((size_t)r * 256 + kc * 32 + c * 8) * 2;
            cp16(sb + SM_TILE(s, t) + r * PITCH + c * 16, src);
        }
        CP_COMMIT();
    };
    // MODE 1: B chunk fp32 load + fold gate*invq (chunk kc == head kc)
    float4 breg[4];
    auto ldB = [&](int kc) {
#pragma unroll
        for (int j = 0; j < 4; j++) {
            int idx = tid + j * 256;
            int r = idx >> 3, c4 = idx & 7;
            int p = nbase + r;
            float f = d_invq[b * HW + p] * d_gate[(size_t)(b * 8 + kc) * HW + p];
            float4 v = *(const float4*)&d_qkvT[((size_t)b * HW + p) * 1024 + kc * 32 + c4 * 4];
            v.x *= f; v.y *= f; v.z *= f; v.w *= f;
            breg[j] = v;
        }
    };
    auto stB = [&](int s) {
#pragma unroll
        for (int j = 0; j < 4; j++) {
            int idx = tid + j * 256;
            int r = idx >> 3, c4 = idx & 7;
            float4 v = breg[j];
            __nv_bfloat16 hx = __float2bfloat16(v.x), hy = __float2bfloat16(v.y);
            __nv_bfloat16 hz = __float2bfloat16(v.z), hw = __float2bfloat16(v.w);
            __nv_bfloat162 h0; h0.x = hx; h0.y = hy;
            __nv_bfloat162 h1; h1.x = hz; h1.y = hw;
            __nv_bfloat162 l0, l1;
            l0.x = __float2bfloat16(v.x - __bfloat162float(hx));
            l0.y = __float2bfloat16(v.y - __bfloat162float(hy));
            l1.x = __float2bfloat16(v.z - __bfloat162float(hz));
            l1.y = __float2bfloat16(v.w - __bfloat162float(hw));
            char* ph = smem + SM_TILE(s, 2) + r * PITCH + c4 * 8;
            char* pl = smem + SM_TILE(s, 3) + r * PITCH + c4 * 8;
            *(__nv_bfloat162*)(ph) = h0; *(__nv_bfloat162*)(ph + 4) = h1;
            *(__nv_bfloat162*)(pl) = l0; *(__nv_bfloat162*)(pl + 4) = l1;
        }
    };

    float acc[4][4][4] = {};
    const int a_row = lane & 15;
    const int a_colh = (lane >> 4) << 3;
    const int b_row = (lane & 7) + ((lane >> 4) << 3);
    const int b_colh = ((lane >> 3) & 1) << 3;

    if (MODE == 0) { load4(0, 0); load4(1, 1); }
    else           { loadA(0, 0); loadA(1, 1); ldB(0); }

#pragma unroll
    for (int i = 0; i < 8; i++) {
        const int s = i & 1;
        if (MODE == 1) stB(s);
        if (i < 6) asm volatile("cp.async.wait_group 1;" ::: "memory");
        else       asm volatile("cp.async.wait_group 0;" ::: "memory");
        __syncthreads();
        if (MODE == 1 && i + 1 < 8) ldB(i + 1);

        const uint32_t tAh = sb + SM_TILE(s, 0), tAl = sb + SM_TILE(s, 1);
        const uint32_t tBh = sb + SM_TILE(s, 2), tBl = sb + SM_TILE(s, 3);
#pragma unroll
        for (int ks = 0; ks < 2; ks++) {
            const int kh = ks * 16;
            uint32_t aH[4][4], aL[4][4], bH[4][2], bL[4][2];
#pragma unroll
            for (int mt = 0; mt < 4; mt++) {
                uint32_t off = (uint32_t)(m0w + mt * 16 + a_row) * PITCH + (kh + a_colh) * 2;
                ldsm4(aH[mt], tAh + off);
                ldsm4(aL[mt], tAl + off);
            }
#pragma unroll
            for (int bt = 0; bt < 2; bt++) {
                uint32_t off = (uint32_t)(n0w + bt * 16 + b_row) * PITCH + (kh + b_colh) * 2;
                uint32_t rh[4], rl[4];
                ldsm4(rh, tBh + off);
                ldsm4(rl, tBl + off);
                bH[bt * 2][0] = rh[0]; bH[bt * 2][1] = rh[1];
                bH[bt * 2 + 1][0] = rh[2]; bH[bt * 2 + 1][1] = rh[3];
                bL[bt * 2][0] = rl[0]; bL[bt * 2][1] = rl[1];
                bL[bt * 2 + 1][0] = rl[2]; bL[bt * 2 + 1][1] = rl[3];
            }
#pragma unroll
            for (int mt = 0; mt < 4; mt++)
#pragma unroll
                for (int nt = 0; nt < 4; nt++) {
                    mma16816(acc[mt][nt], aH[mt], bH[nt][0], bH[nt][1]);
                    mma16816(acc[mt][nt], aH[mt], bL[nt][0], bL[nt][1]);
                    mma16816(acc[mt][nt], aL[mt], bH[nt][0], bH[nt][1]);
                }
        }
        __syncthreads();
        if (i + 2 < 8) { if (MODE == 0) load4(i + 2, s); else loadA(i + 2, s); }
    }

    if (MODE == 0) {
        // transposed epilogue via smem: sT[px][ch] (pitch 132 floats)
        float* sT = (float*)smem;
        __syncthreads();
#pragma unroll
        for (int mt = 0; mt < 4; mt++) {
            int rr0 = m0w + mt * 16 + (lane >> 2);
            int rr1 = rr0 + 8;
            float b0 = d_ball[mbase + rr0], b1 = d_ball[mbase + rr1];
#pragma unroll
            for (int nt = 0; nt < 4; nt++) {
                int cc = n0w + nt * 8 + (lane & 3) * 2;
                sT[(cc) * 132 + rr0]     = acc[mt][nt][0] + b0;
                sT[(cc + 1) * 132 + rr0] = acc[mt][nt][1] + b0;
                sT[(cc) * 132 + rr1]     = acc[mt][nt][2] + b1;
                sT[(cc + 1) * 132 + rr1] = acc[mt][nt][3] + b1;
            }
        }
        __syncthreads();
#pragma unroll
        for (int j = 0; j < 16; j++) {
            int idx = tid + j * 256;
            int px = idx >> 5, c4 = idx & 31;
            float4 v = *(float4*)&sT[px * 132 + c4 * 4];
            *(float4*)&d_qkvT[((size_t)b * HW + nbase + px) * 1024 + mbase + c4 * 4] = v;
        }
        if (mbase < 512 && tid < 128) {
            int px = tid;
            float s = 0.f;
#pragma unroll
            for (int c4 = 0; c4 < 32; c4++) {
                float4 v = *(float4*)&sT[px * 132 + c4 * 4];
                s += v.x * v.x + v.y * v.y + v.z * v.z + v.w * v.w;
            }
            d_ssqp[(size_t)(mbase >> 7) * (B_ * HW) + b * HW + nbase + px] = s;
        }
    } else {
        // BN + relu epilogue, row-major out [b][c][p]
        float* Cg = CoutExt + (size_t)b * 256 * HW;
#pragma unroll
        for (int mt = 0; mt < 4; mt++) {
            int r0 = mbase + m0w + mt * 16 + (lane >> 2);
            int r1 = r0 + 8;
            float sc0 = d_s[r0], t0 = d_t[r0], sc1 = d_s[r1], t1 = d_t[r1];
#pragma unroll
            for (int nt = 0; nt < 4; nt++) {
                int c = nbase + n0w + nt * 8 + (lane & 3) * 2;
                float2 o0, o1;
                o0.x = fmaxf(acc[mt][nt][0] * sc0 + t0, 0.f);
                o0.y = fmaxf(acc[mt][nt][1] * sc0 + t0, 0.f);
                o1.x = fmaxf(acc[mt][nt][2] * sc1 + t1, 0.f);
                o1.y = fmaxf(acc[mt][nt][3] * sc1 + t1, 0.f);
                *(float2*)&Cg[(size_t)r0 * HW + c] = o0;
                *(float2*)&Cg[(size_t)r1 * HW + c] = o1;
            }
        }
    }
}

// ---------------- K2s: finish pixelnorm factors --------------------------------
__global__ void k2s() {
    int i = blockIdx.x * blockDim.x + threadIdx.x;
    float sq = d_ssqp[i] + d_ssqp[B_ * HW + i];
    float sk = d_ssqp[2 * B_ * HW + i] + d_ssqp[3 * B_ * HW + i];
    d_invq[i] = rsqrtf(sq * (1.f / 256.f) + 1e-8f);
    d_invk[i] = rsqrtf(sk * (1.f / 256.f) + 1e-8f);
}

// ---------------- K3a: per-head partial kv = (k*invk) @ v^T (pixel-major) ------
__global__ __launch_bounds__(256) void k3a_kv() {
    int head = blockIdx.y, split = blockIdx.x;
    int b = head >> 3, h = head & 7;

    __shared__ float ks[128][32];
    __shared__ float vs[128][64];

    int tid = threadIdx.x;
    int tx = tid & 15, ty = tid >> 4;
    float acc[2][4] = {};

    for (int it = 0; it < 4; it++) {
        int pb = split * 512 + it * 128;
#pragma unroll
        for (int j = 0; j < 4; j++) {
            int idx = tid + j * 256;
            int r = idx >> 3, c4 = idx & 7;
            int p = pb + r;
            float iv = d_invk[b * HW + p];
            float4 v = *(const float4*)&d_qkvT[((size_t)b * HW + p) * 1024 + 256 + h * 32 + c4 * 4];
            v.x *= iv; v.y *= iv; v.z *= iv; v.w *= iv;
            *(float4*)&ks[r][c4 * 4] = v;
        }
#pragma unroll
        for (int j = 0; j < 8; j++) {
            int idx = tid + j * 256;
            int r = idx >> 4, c4 = idx & 15;
            int p = pb + r;
            float4 v = *(const float4*)&d_qkvT[((size_t)b * HW + p) * 1024 + 512 + h * 64 + c4 * 4];
            *(float4*)&vs[r][c4 * 4] = v;
        }
        __syncthreads();
#pragma unroll 4
        for (int p = 0; p < 128; p++) {
            float4 v4 = *(const float4*)&vs[p][tx * 4];
            float k0 = ks[p][ty * 2], k1 = ks[p][ty * 2 + 1];
            acc[0][0] += k0 * v4.x; acc[0][1] += k0 * v4.y;
            acc[0][2] += k0 * v4.z; acc[0][3] += k0 * v4.w;
            acc[1][0] += k1 * v4.x; acc[1][1] += k1 * v4.y;
            acc[1][2] += k1 * v4.z; acc[1][3] += k1 * v4.w;
        }
        __syncthreads();
    }
    float* out = d_kvpart + ((size_t)head * 8 + split) * 2048;
#pragma unroll
    for (int i = 0; i < 2; i++)
#pragma unroll
        for (int j = 0; j < 4; j++)
            out[(ty * 2 + i) * 64 + tx * 4 + j] = acc[i][j];
}

// ---------------- K3b: reduce kv, pixelnorm, m, Wf2 ----------------------------
__global__ __launch_bounds__(256) void k3b_kvnorm(const float* __restrict__ Wf) {
    int head = blockIdx.x;
    int b = head >> 3, h = head & 7;
    __shared__ float skv[2048];
    __shared__ float nrm[64];
    int tid = threadIdx.x;
#pragma unroll
    for (int s = 0; s < 8; s++) {
        int idx = tid + s * 256;
        float sum = 0.f;
#pragma unroll
        for (int sp = 0; sp < 8; sp++)
            sum += d_kvpart[(size_t)(head * 8 + sp) * 2048 + idx];
        skv[idx] = sum;
    }
    __syncthreads();
    if (tid < 64) {
        float s = 0.f;
#pragma unroll
        for (int c = 0; c < 32; c++) { float v = skv[c * 64 + tid]; s += v * v; }
        nrm[tid] = rsqrtf(s * (1.f / 32.f) + 1e-8f);
    }
    __syncthreads();
#pragma unroll
    for (int s = 0; s < 8; s++) {
        int idx = tid + s * 256;
        skv[idx] *= nrm[idx & 63];
    }
    __syncthreads();
    if (tid < 32) {
        float s = 0.f;
#pragma unroll
        for (int C = 32; C < 64; C++) s += skv[tid * 64 + C];
        d_m[head * 32 + tid] = s * (1.f / 32.f);
    }
    int o = tid;
    float wf[32];
#pragma unroll
    for (int c2 = 0; c2 < 32; c2++) wf[c2] = Wf[o * 256 + h * 32 + c2];
    float* out = d_Wf2 + (size_t)b * 65536 + o * 256 + h * 32;
    for (int c = 0; c < 32; c++) {
        float s = 0.f;
#pragma unroll
        for (int c2 = 0; c2 < 32; c2++) s += wf[c2] * skv[c * 64 + c2];
        out[c] = s;
    }
}

// ---------------- K4: spatial softmax gate (pixel-major q) ----------------------
__global__ __launch_bounds__(256) void k4_gate() {
    int head = blockIdx.x;
    int b = head >> 3, h = head & 7;
    __shared__ float4 m4[8];
    __shared__ float red[256];
    int tid = threadIdx.x;
    if (tid < 8) m4[tid] = *(const float4*)&d_m[head * 32 + tid * 4];
    __syncthreads();

    float z[16];
    float lmax = -1e30f;
#pragma unroll
    for (int i = 0; i < 16; i++) {
        int p = tid + i * 256;
        const float4* row = (const float4*)&d_qkvT[((size_t)b * HW + p) * 1024 + h * 32];
        float s = 0.f;
#pragma unroll
        for (int c4 = 0; c4 < 8; c4++) {
            float4 q = row[c4], m = m4[c4];
            s += q.x * m.x + q.y * m.y + q.z * m.z + q.w * m.w;
        }
        z[i] = s * d_invq[b * HW + p] * (1.f / 64.f);
        lmax = fmaxf(lmax, z[i]);
    }
    red[tid] = lmax; __syncthreads();
    for (int st = 128; st > 0; st >>= 1) {
        if (tid < st) red[tid] = fmaxf(red[tid], red[tid + st]);
        __syncthreads();
    }
    float gmax = red[0]; __syncthreads();
    float lsum = 0.f;
#pragma unroll
    for (int i = 0; i < 16; i++) { z[i] = __expf(z[i] - gmax); lsum += z[i]; }
    red[tid] = lsum; __syncthreads();
    for (int st = 128; st > 0; st >>= 1) {
        if (tid < st) red[tid] += red[tid + st];
        __syncthreads();
    }
    float inv = 1.f / red[0];
#pragma unroll
    for (int i = 0; i < 16; i++)
        d_gate[(size_t)head * HW + tid + i * 256] = z[i] * inv;
}

// ---------------- launch --------------------------------------------------------
extern "C" void kernel_launch(void* const* d_in, const int* in_sizes, int n_in,
                              void* d_out, int out_size) {
    const float* x     = (const float*)d_in[0];
    const float* Wq    = (const float*)d_in[1];
    const float* bq    = (const float*)d_in[2];
    const float* Wk    = (const float*)d_in[3];
    const float* bk    = (const float*)d_in[4];
    const float* Wv    = (const float*)d_in[5];
    const float* bv    = (const float*)d_in[6];
    const float* Wf    = (const float*)d_in[7];
    const float* bf    = (const float*)d_in[8];
    const float* gamma = (const float*)d_in[9];
    const float* beta  = (const float*)d_in[10];
    const float* mean  = (const float*)d_in[11];
    const float* var   = (const float*)d_in[12];
    float* out = (float*)d_out;

    static bool attr_set = false;
    if (!attr_set) {
        cudaFuncSetAttribute(k_mma<0>, cudaFuncAttributeMaxDynamicSharedMemorySize, SMEM_SZ);
        cudaFuncSetAttribute(k_mma<1>, cudaFuncAttributeMaxDynamicSharedMemorySize, SMEM_SZ);
        attr_set = true;
    }

    k0_prep<<<(1024 * 256 + 255) / 256, 256>>>(Wq, bq, Wk, bk, Wv, bv, bf, gamma, beta, mean, var);
    k_convx<<<dim3(128, 4, B_), 256>>>(x);
    k_mma<0><<<dim3(32, 8, B_), 256, SMEM_SZ>>>(nullptr);
    k2s<<<256, 128>>>();
    k3a_kv<<<dim3(8, 64), 256>>>();
    k3b_kvnorm<<<64, 256>>>(Wf);
    k_convw2<<<(B_ * 65536) / 256, 256>>>();
    k4_gate<<<64, 256>>>();
    k_mma<1><<<dim3(32, 2, B_), 256, SMEM_SZ>>>(out);
}